// round 11
// baseline (speedup 1.0000x reference)
#include <cuda_runtime.h>
#include <math.h>

#define NB   16
#define NL   1024
#define ND   512
#define NDH  64
#define KTOP 13

// Scratch (no allocations allowed): 4 x 4MB fp32
__device__ float g_qp[NB * NDH * NL];   // q projection, [b][d][l]
__device__ float g_kp[NB * NDH * NL];   // k projection, [b][d][l]
__device__ float g_vp[NB * NDH * NL];   // v projection, [b][d][l]
__device__ float g_agg[NB * NDH * NL];  // aggregated result, [b][d][l]

// ---- bf16 split helpers (truncation split) --------------------------------
__device__ __forceinline__ void split_dup(float x, unsigned& wh, unsigned& wl) {
    unsigned u = __float_as_uint(x);
    float hi = __uint_as_float(u & 0xFFFF0000u);
    unsigned lu = __float_as_uint(x - hi);
    wh = __byte_perm(u,  u,  0x3232);
    wl = __byte_perm(lu, lu, 0x3232);
}
__device__ __forceinline__ unsigned split_pack(float x) {
    unsigned u = __float_as_uint(x);
    float hi = __uint_as_float(u & 0xFFFF0000u);
    unsigned lu = __float_as_uint(x - hi);
    return __byte_perm(u, lu, 0x7632);
}

__device__ __forceinline__ void mma_bf16(float* c, const unsigned* a,
                                         unsigned b0, unsigned b1) {
    asm volatile(
        "mma.sync.aligned.m16n8k16.row.col.f32.bf16.bf16.f32 "
        "{%0,%1,%2,%3}, {%4,%5,%6,%7}, {%8,%9}, {%0,%1,%2,%3};\n"
        : "+f"(c[0]), "+f"(c[1]), "+f"(c[2]), "+f"(c[3])
        : "r"(a[0]), "r"(a[1]), "r"(a[2]), "r"(a[3]), "r"(b0), "r"(b1));
}

__device__ __forceinline__ int smidx(int row, int w) {
    return row * 32 + (((w >> 3) ^ (row & 3)) << 3)
         + ((w & 7) ^ (((row >> 2) & 1) << 2));
}

// ---------------------------------------------------------------------------
// Kernel 1: projection via bf16 tensor cores, split-K doubling.
// R7 structure (BK=32, single-buffered static smem, register prefetch) but
// 512 threads / 16 warps: each warp owns a 32(d) x 16(l) C-tile, doubling
// warps per scheduler to hide LDS/HMMA latency. grid (NL/128, NB, 3).
// ---------------------------------------------------------------------------
__global__ __launch_bounds__(512) void proj_kernel(
    const float* __restrict__ Q, const float* __restrict__ K,
    const float* __restrict__ V, const float* __restrict__ Wq,
    const float* __restrict__ bq)
{
    __shared__ unsigned Ws[64 * 32];    // A: (hiW,loW) interleaved words
    __shared__ unsigned Xh[128 * 32];   // B plane: (hiX,hiX)
    __shared__ unsigned Xl[128 * 32];   // B plane: (loX,loX)

    const int b    = blockIdx.y;
    const int l0   = blockIdx.x * 128;
    const int mat  = blockIdx.z;
    const int tid  = threadIdx.x;
    const int wid  = tid >> 5;          // 0..15
    const int lane = tid & 31;
    const int g    = lane >> 2;
    const int cq   = lane & 3;
    const int m_base = (wid & 1) * 32;  // d half
    const int n_base = (wid >> 1) * 16; // l sixteenth

    const float* src = (mat == 0 ? Q : (mat == 1 ? K : V))
                     + ((size_t)b * NL + l0) * ND;
    float* dst = (mat == 0 ? g_qp : (mat == 1 ? g_kp : g_vp))
               + (size_t)b * NDH * NL + l0;

    // X staging: 1024 float4 per chunk -> 2 per thread
    int xgb[2], xsb[2];
    #pragma unroll
    for (int i = 0; i < 2; ++i) {
        int f4id = tid + i * 512;
        int r    = f4id >> 3;           // l row 0..127
        int c4   = f4id & 7;            // k f4-col
        xgb[i]   = r * ND + c4 * 4;
        xsb[i]   = r * 32 + (((c4 >> 1) ^ (r & 3)) << 3)
                 + (((c4 & 1) << 2) ^ (((r >> 2) & 1) << 2));
    }
    // W staging: 512 quads per chunk -> 1 per thread
    const int wdd = tid & 63;
    const int wkq = tid >> 6;           // 0..7
    const int wsb = wdd * 32 + (((wkq >> 1) ^ (wdd & 3)) << 3)
                  + (((wkq & 1) << 2) ^ (((wdd >> 2) & 1) << 2));

    float acc[2][2][4];
    #pragma unroll
    for (int mt = 0; mt < 2; ++mt)
        #pragma unroll
        for (int nt = 0; nt < 2; ++nt)
            #pragma unroll
            for (int r = 0; r < 4; ++r) acc[mt][nt][r] = 0.f;

    float4 xR[2];
    float  wF[4];
    #pragma unroll
    for (int i = 0; i < 2; ++i)
        xR[i] = *reinterpret_cast<const float4*>(src + xgb[i]);
    #pragma unroll
    for (int j = 0; j < 4; ++j)
        wF[j] = Wq[(size_t)(wkq * 4 + j) * NDH + wdd];

    for (int ch = 0; ch < 16; ++ch) {
        // stage chunk ch
        #pragma unroll
        for (int i = 0; i < 2; ++i) {
            unsigned h0,h1,h2,h3, q0,q1,q2,q3;
            split_dup(xR[i].x, h0, q0);
            split_dup(xR[i].y, h1, q1);
            split_dup(xR[i].z, h2, q2);
            split_dup(xR[i].w, h3, q3);
            *reinterpret_cast<uint4*>(&Xh[xsb[i]]) = make_uint4(h0,h1,h2,h3);
            *reinterpret_cast<uint4*>(&Xl[xsb[i]]) = make_uint4(q0,q1,q2,q3);
        }
        *reinterpret_cast<uint4*>(&Ws[wsb]) = make_uint4(
            split_pack(wF[0]), split_pack(wF[1]),
            split_pack(wF[2]), split_pack(wF[3]));
        __syncthreads();

        // prefetch chunk ch+1
        if (ch < 15) {
            const int ko = (ch + 1) * 32;
            #pragma unroll
            for (int i = 0; i < 2; ++i)
                xR[i] = *reinterpret_cast<const float4*>(src + xgb[i] + ko);
            #pragma unroll
            for (int j = 0; j < 4; ++j)
                wF[j] = Wq[(size_t)(ko + wkq * 4 + j) * NDH + wdd];
        }

        // compute chunk ch: 4 k-steps x 2 planes x (2 mt x 2 nt)
        #pragma unroll
        for (int ks = 0; ks < 4; ++ks) {
            unsigned a[2][4];
            #pragma unroll
            for (int mt = 0; mt < 2; ++mt) {
                int r0 = m_base + mt * 16 + g;
                a[mt][0] = Ws[smidx(r0,     ks * 8 + cq)];
                a[mt][1] = Ws[smidx(r0 + 8, ks * 8 + cq)];
                a[mt][2] = Ws[smidx(r0,     ks * 8 + cq + 4)];
                a[mt][3] = Ws[smidx(r0 + 8, ks * 8 + cq + 4)];
            }
            #pragma unroll
            for (int nt = 0; nt < 2; ++nt) {
                int rn = n_base + nt * 8 + g;
                unsigned bh0 = Xh[smidx(rn, ks * 8 + cq)];
                unsigned bh1 = Xh[smidx(rn, ks * 8 + cq + 4)];
                unsigned bl0 = Xl[smidx(rn, ks * 8 + cq)];
                unsigned bl1 = Xl[smidx(rn, ks * 8 + cq + 4)];
                #pragma unroll
                for (int mt = 0; mt < 2; ++mt) {
                    mma_bf16(acc[mt][nt], a[mt], bh0, bh1);   // W * hiX
                    mma_bf16(acc[mt][nt], a[mt], bl0, bl1);   // W * loX
                }
            }
        }
        __syncthreads();
    }

    // epilogue: bias + transposed coalesced STG.64
    #pragma unroll
    for (int mt = 0; mt < 2; ++mt) {
        int d0 = m_base + mt * 16 + g;
        float bLo = bq[d0];
        float bHi = bq[d0 + 8];
        #pragma unroll
        for (int nt = 0; nt < 2; ++nt) {
            int l = n_base + nt * 8 + 2 * cq;
            float2 r0 = make_float2(acc[mt][nt][0] + bLo, acc[mt][nt][1] + bLo);
            float2 r1 = make_float2(acc[mt][nt][2] + bHi, acc[mt][nt][3] + bHi);
            *reinterpret_cast<float2*>(dst + (size_t)d0 * NL + l)       = r0;
            *reinterpret_cast<float2*>(dst + (size_t)(d0 + 8) * NL + l) = r1;
        }
    }
}

// ---------------------------------------------------------------------------
// Kernel 2: corr via FFT (reference algorithm):
//   corr = real(ifft(fft(q) * conj(fft(k))))
// Two series (d0, d0+1) per CTA, 128 threads. (unchanged from R7)
// ---------------------------------------------------------------------------
__global__ __launch_bounds__(128) void corr_kernel()
{
    __shared__ __align__(16) float2 fbuf[4096];   // 32 KB workspace
    __shared__ float2 tw[512];
    __shared__ float s_tv[2][KTOP];
    __shared__ int   s_ti[2][KTOP];
    __shared__ float s_w[2][KTOP];
    __shared__ float red_v[4];
    __shared__ int   red_i[4];

    const int b   = blockIdx.y;
    const int d0  = blockIdx.x * 2;
    const int tid = threadIdx.x;
    float* fbf = reinterpret_cast<float*>(fbuf);
    const size_t offA = ((size_t)b * NDH + d0) * NL;

    for (int j = tid; j < 512; j += 128) {
        float s, c;
        sincospif(-(float)j / 512.0f, &s, &c);
        tw[j] = make_float2(c, s);
    }
    {
        const float4* qa = reinterpret_cast<const float4*>(g_qp + offA);
        const float4* ka = reinterpret_cast<const float4*>(g_kp + offA);
        for (int i = tid; i < 512; i += 128) {
            float4 q = qa[i], k = ka[i];
            int o = i * 4;
            fbuf[o+0] = make_float2(q.x, k.x);
            fbuf[o+1] = make_float2(q.y, k.y);
            fbuf[o+2] = make_float2(q.z, k.z);
            fbuf[o+3] = make_float2(q.w, k.w);
        }
    }
    __syncthreads();

    // forward FFT, both series at once, ping-pong 0<->2048
    int src = 0;
    for (int st = 0; st < 10; ++st) {
        const int s = 1 << st;
        const int dst = src ^ 2048;
        #pragma unroll 2
        for (int it = 0; it < 8; ++it) {
            int t  = tid + it * 128;
            int so = (t >> 9) << 10;
            int u  = t & 511;
            int j  = u & ~(s - 1);
            float2 a  = fbuf[src + so + u];
            float2 bb = fbuf[src + so + u + 512];
            float2 w  = tw[j];
            float2 df = make_float2(a.x - bb.x, a.y - bb.y);
            fbuf[dst + so + u + j]     = make_float2(a.x + bb.x, a.y + bb.y);
            fbuf[dst + so + u + j + s] = make_float2(w.x*df.x - w.y*df.y,
                                                     w.x*df.y + w.y*df.x);
        }
        __syncthreads();
        src = dst;
    }

    // spectral: S = Q * conj(K); T = S_a + i*S_b; store conj(T) in [2048,3072)
    for (int it = 0; it < 8; ++it) {
        int f  = tid + it * 128;
        int fn = (1024 - f) & 1023;
        float2 Za = fbuf[f],        Zan = fbuf[fn];
        float2 Zb = fbuf[1024 + f], Zbn = fbuf[1024 + fn];
        float qx = 0.5f*(Za.x + Zan.x), qy = 0.5f*(Za.y - Zan.y);
        float kx = 0.5f*(Za.y + Zan.y), ky = -0.5f*(Za.x - Zan.x);
        float sax = qx*kx + qy*ky, say = qy*kx - qx*ky;
        float qx2 = 0.5f*(Zb.x + Zbn.x), qy2 = 0.5f*(Zb.y - Zbn.y);
        float kx2 = 0.5f*(Zb.y + Zbn.y), ky2 = -0.5f*(Zb.x - Zbn.x);
        float sbx = qx2*kx2 + qy2*ky2, sby = qy2*kx2 - qx2*ky2;
        fbuf[2048 + f] = make_float2(sax - sby, -(say + sbx));
    }
    __syncthreads();

    // load v for both series into floats [6144,8192)
    {
        const float4* va = reinterpret_cast<const float4*>(g_vp + offA);
        for (int i = tid; i < 512; i += 128)
            *reinterpret_cast<float4*>(&fbf[6144 + i * 4]) = va[i];
    }

    // inverse FFT (forward FFT of conj T), ping-pong [2048,3072) <-> [0,1024)
    int s2 = 2048;
    for (int st = 0; st < 10; ++st) {
        const int s = 1 << st;
        const int dst = (s2 == 2048) ? 0 : 2048;
        #pragma unroll 2
        for (int it = 0; it < 4; ++it) {
            int u = tid + it * 128;
            int j = u & ~(s - 1);
            float2 a  = fbuf[s2 + u];
            float2 bb = fbuf[s2 + u + 512];
            float2 w  = tw[j];
            float2 df = make_float2(a.x - bb.x, a.y - bb.y);
            fbuf[dst + u + j]     = make_float2(a.x + bb.x, a.y + bb.y);
            fbuf[dst + u + j + s] = make_float2(w.x*df.x - w.y*df.y,
                                                w.x*df.y + w.y*df.x);
        }
        __syncthreads();
        s2 = dst;
    }

    const float invN = 1.0f / 1024.0f;
    for (int it = 0; it < 8; ++it) {
        int n = tid + it * 128;
        float2 F = fbuf[2048 + n];
        fbf[n]        =  F.x * invN;
        fbf[1024 + n] = -F.y * invN;
    }
    __syncthreads();

    // top-13 per series: warps 0-1 -> series A, warps 2-3 -> series B
    const int sid = tid >> 6;
    const int lt  = tid & 63;
    float* sc = fbf + (sid << 10);
    const int base = lt * 16;
    for (int p = 0; p < KTOP; ++p) {
        float bv = -3.0e38f; int bi = 0;
        #pragma unroll
        for (int jj = 0; jj < 16; ++jj) {
            float v = sc[base + jj];
            if (v > bv) { bv = v; bi = base + jj; }
        }
        #pragma unroll
        for (int off = 16; off > 0; off >>= 1) {
            float ov = __shfl_down_sync(0xffffffffu, bv, off);
            int   oi = __shfl_down_sync(0xffffffffu, bi, off);
            if (ov > bv || (ov == bv && oi < bi)) { bv = ov; bi = oi; }
        }
        if ((tid & 31) == 0) { red_v[tid >> 5] = bv; red_i[tid >> 5] = bi; }
        __syncthreads();
        if (lt == 0) {
            float v0 = red_v[sid * 2]; int i0 = red_i[sid * 2];
            float v1 = red_v[sid * 2 + 1]; int i1 = red_i[sid * 2 + 1];
            if (v1 > v0 || (v1 == v0 && i1 < i0)) { v0 = v1; i0 = i1; }
            s_tv[sid][p] = v0; s_ti[sid][p] = i0;
            sc[i0] = -3.4e38f;
        }
        __syncthreads();
    }

    if (lt == 0) {
        float mx = s_tv[sid][0];
        float e[KTOP], sum = 0.f;
        #pragma unroll
        for (int p = 0; p < KTOP; ++p) { e[p] = expf(s_tv[sid][p] - mx); sum += e[p]; }
        float inv = 1.0f / sum;
        #pragma unroll
        for (int p = 0; p < KTOP; ++p) s_w[sid][p] = e[p] * inv;
    }
    __syncthreads();

    const float* sv = fbf + 6144 + (sid << 10);
    float* aggrow = g_agg + offA + (size_t)sid * NL;
    float wgt[KTOP]; int ix[KTOP];
    #pragma unroll
    for (int p = 0; p < KTOP; ++p) { wgt[p] = s_w[sid][p]; ix[p] = s_ti[sid][p]; }
    #pragma unroll
    for (int jj = 0; jj < 16; ++jj) {
        int l = lt + jj * 64;
        float acc = 0.f;
        #pragma unroll
        for (int p = 0; p < KTOP; ++p)
            acc += wgt[p] * sv[(l + ix[p]) & 1023];
        aggrow[l] = acc;
    }
}

// ---------------------------------------------------------------------------
// Kernel 3: transpose-broadcast agg[b][d][l] -> out[b][l][h*64+d], h=0..7
// ---------------------------------------------------------------------------
__global__ __launch_bounds__(256) void out_kernel(float* __restrict__ out)
{
    __shared__ float t[64][33];
    const int b   = blockIdx.y;
    const int l0  = blockIdx.x * 32;
    const int tid = threadIdx.x;
    const float* agg = g_agg + (size_t)b * NDH * NL;

    #pragma unroll
    for (int i = 0; i < 8; ++i) {
        int flat = tid + i * 256;
        int dd   = flat >> 5;
        int ll   = flat & 31;
        t[dd][ll] = agg[(size_t)dd * NL + l0 + ll];
    }
    __syncthreads();

    float* obase = out + ((size_t)b * NL + l0) * (NDH * 8);
    #pragma unroll
    for (int i = 0; i < 16; ++i) {
        int f4  = tid + i * 256;
        int ll  = f4 >> 7;
        int c0  = (f4 & 127) * 4;
        int cc  = c0 & 63;
        float4 v = make_float4(t[cc][ll], t[cc + 1][ll], t[cc + 2][ll], t[cc + 3][ll]);
        *reinterpret_cast<float4*>(obase + (size_t)ll * 512 + c0) = v;
    }
}

// ---------------------------------------------------------------------------
extern "C" void kernel_launch(void* const* d_in, const int* in_sizes, int n_in,
                              void* d_out, int out_size)
{
    const float* Q  = (const float*)d_in[0];
    const float* K  = (const float*)d_in[1];
    const float* V  = (const float*)d_in[2];
    const float* Wq = (const float*)d_in[3];
    const float* bq = (const float*)d_in[4];
    float* out = (float*)d_out;

    proj_kernel<<<dim3(NL / 128, NB, 3), 512>>>(Q, K, V, Wq, bq);
    corr_kernel<<<dim3(NDH / 2, NB), 128>>>();
    out_kernel<<<dim3(NL / 32, NB), 256>>>(out);
}

// round 13
// speedup vs baseline: 1.0408x; 1.0408x over previous
#include <cuda_runtime.h>
#include <math.h>

#define NB   16
#define NL   1024
#define ND   512
#define NDH  64
#define KTOP 13

// Scratch (no allocations allowed): 4 x 4MB fp32
__device__ float g_qp[NB * NDH * NL];   // q projection, [b][d][l]
__device__ float g_kp[NB * NDH * NL];   // k projection, [b][d][l]
__device__ float g_vp[NB * NDH * NL];   // v projection, [b][d][l]
__device__ float g_agg[NB * NDH * NL];  // aggregated result, [b][d][l]

// ---- bf16 split helpers (truncation split) --------------------------------
__device__ __forceinline__ void split_dup(float x, unsigned& wh, unsigned& wl) {
    unsigned u = __float_as_uint(x);
    float hi = __uint_as_float(u & 0xFFFF0000u);
    unsigned lu = __float_as_uint(x - hi);
    wh = __byte_perm(u,  u,  0x3232);
    wl = __byte_perm(lu, lu, 0x3232);
}
__device__ __forceinline__ unsigned split_pack(float x) {
    unsigned u = __float_as_uint(x);
    float hi = __uint_as_float(u & 0xFFFF0000u);
    unsigned lu = __float_as_uint(x - hi);
    return __byte_perm(u, lu, 0x7632);
}

__device__ __forceinline__ void mma_bf16(float* c, const unsigned* a,
                                         unsigned b0, unsigned b1) {
    asm volatile(
        "mma.sync.aligned.m16n8k16.row.col.f32.bf16.bf16.f32 "
        "{%0,%1,%2,%3}, {%4,%5,%6,%7}, {%8,%9}, {%0,%1,%2,%3};\n"
        : "+f"(c[0]), "+f"(c[1]), "+f"(c[2]), "+f"(c[3])
        : "r"(a[0]), "r"(a[1]), "r"(a[2]), "r"(a[3]), "r"(b0), "r"(b1));
}

__device__ __forceinline__ int smidx(int row, int w) {
    return row * 32 + (((w >> 3) ^ (row & 3)) << 3)
         + ((w & 7) ^ (((row >> 2) & 1) << 2));
}

// ---------------------------------------------------------------------------
// Kernel 1: projection via bf16 tensor cores, split-K doubling.
// R7 exact (best measured: 56.8us). BK=32, single-buffered static smem,
// register prefetch. grid (NL/128, NB, 3), 256 threads.
// ---------------------------------------------------------------------------
__global__ __launch_bounds__(256) void proj_kernel(
    const float* __restrict__ Q, const float* __restrict__ K,
    const float* __restrict__ V, const float* __restrict__ Wq,
    const float* __restrict__ bq)
{
    __shared__ unsigned Ws[64 * 32];
    __shared__ unsigned Xh[128 * 32];
    __shared__ unsigned Xl[128 * 32];

    const int b    = blockIdx.y;
    const int l0   = blockIdx.x * 128;
    const int mat  = blockIdx.z;
    const int tid  = threadIdx.x;
    const int wid  = tid >> 5;
    const int lane = tid & 31;
    const int g    = lane >> 2;
    const int cq   = lane & 3;
    const int m_base = (wid >> 2) * 32;
    const int n_base = (wid & 3) * 32;

    const float* src = (mat == 0 ? Q : (mat == 1 ? K : V))
                     + ((size_t)b * NL + l0) * ND;
    float* dst = (mat == 0 ? g_qp : (mat == 1 ? g_kp : g_vp))
               + (size_t)b * NDH * NL + l0;

    int xgb[4], xsb[4];
    #pragma unroll
    for (int i = 0; i < 4; ++i) {
        int f4id = tid + i * 256;
        int r    = f4id >> 3;
        int c4   = f4id & 7;
        xgb[i]   = r * ND + c4 * 4;
        xsb[i]   = r * 32 + (((c4 >> 1) ^ (r & 3)) << 3)
                 + (((c4 & 1) << 2) ^ (((r >> 2) & 1) << 2));
    }
    int wdd[2], wkq[2], wsb[2];
    #pragma unroll
    for (int i = 0; i < 2; ++i) {
        int qid = tid + i * 256;
        wdd[i]  = qid & 63;
        wkq[i]  = qid >> 6;
        wsb[i]  = wdd[i] * 32 + (((wkq[i] >> 1) ^ (wdd[i] & 3)) << 3)
                + (((wkq[i] & 1) << 2) ^ (((wdd[i] >> 2) & 1) << 2));
    }

    float acc[2][4][4];
    #pragma unroll
    for (int mt = 0; mt < 2; ++mt)
        #pragma unroll
        for (int nt = 0; nt < 4; ++nt)
            #pragma unroll
            for (int r = 0; r < 4; ++r) acc[mt][nt][r] = 0.f;

    float4 xR[4];
    float  wF[8];
    #pragma unroll
    for (int i = 0; i < 4; ++i)
        xR[i] = *reinterpret_cast<const float4*>(src + xgb[i]);
    #pragma unroll
    for (int i = 0; i < 2; ++i)
        #pragma unroll
        for (int j = 0; j < 4; ++j)
            wF[i * 4 + j] = Wq[(size_t)(wkq[i] * 4 + j) * NDH + wdd[i]];

    for (int ch = 0; ch < 16; ++ch) {
        #pragma unroll
        for (int i = 0; i < 4; ++i) {
            unsigned h0,h1,h2,h3, q0,q1,q2,q3;
            split_dup(xR[i].x, h0, q0);
            split_dup(xR[i].y, h1, q1);
            split_dup(xR[i].z, h2, q2);
            split_dup(xR[i].w, h3, q3);
            *reinterpret_cast<uint4*>(&Xh[xsb[i]]) = make_uint4(h0,h1,h2,h3);
            *reinterpret_cast<uint4*>(&Xl[xsb[i]]) = make_uint4(q0,q1,q2,q3);
        }
        #pragma unroll
        for (int i = 0; i < 2; ++i) {
            *reinterpret_cast<uint4*>(&Ws[wsb[i]]) = make_uint4(
                split_pack(wF[i*4+0]), split_pack(wF[i*4+1]),
                split_pack(wF[i*4+2]), split_pack(wF[i*4+3]));
        }
        __syncthreads();

        if (ch < 15) {
            const int ko = (ch + 1) * 32;
            #pragma unroll
            for (int i = 0; i < 4; ++i)
                xR[i] = *reinterpret_cast<const float4*>(src + xgb[i] + ko);
            #pragma unroll
            for (int i = 0; i < 2; ++i)
                #pragma unroll
                for (int j = 0; j < 4; ++j)
                    wF[i * 4 + j] = Wq[(size_t)(ko + wkq[i] * 4 + j) * NDH + wdd[i]];
        }

        #pragma unroll
        for (int ks = 0; ks < 4; ++ks) {
            unsigned a[2][4];
            #pragma unroll
            for (int mt = 0; mt < 2; ++mt) {
                int r0 = m_base + mt * 16 + g;
                a[mt][0] = Ws[smidx(r0,     ks * 8 + cq)];
                a[mt][1] = Ws[smidx(r0 + 8, ks * 8 + cq)];
                a[mt][2] = Ws[smidx(r0,     ks * 8 + cq + 4)];
                a[mt][3] = Ws[smidx(r0 + 8, ks * 8 + cq + 4)];
            }
            #pragma unroll
            for (int nt = 0; nt < 4; ++nt) {
                int rn = n_base + nt * 8 + g;
                unsigned bh0 = Xh[smidx(rn, ks * 8 + cq)];
                unsigned bh1 = Xh[smidx(rn, ks * 8 + cq + 4)];
                unsigned bl0 = Xl[smidx(rn, ks * 8 + cq)];
                unsigned bl1 = Xl[smidx(rn, ks * 8 + cq + 4)];
                #pragma unroll
                for (int mt = 0; mt < 2; ++mt) {
                    mma_bf16(acc[mt][nt], a[mt], bh0, bh1);
                    mma_bf16(acc[mt][nt], a[mt], bl0, bl1);
                }
            }
        }
        __syncthreads();
    }

    #pragma unroll
    for (int mt = 0; mt < 2; ++mt) {
        int d0 = m_base + mt * 16 + g;
        float bLo = bq[d0];
        float bHi = bq[d0 + 8];
        #pragma unroll
        for (int nt = 0; nt < 4; ++nt) {
            int l = n_base + nt * 8 + 2 * cq;
            float2 r0 = make_float2(acc[mt][nt][0] + bLo, acc[mt][nt][1] + bLo);
            float2 r1 = make_float2(acc[mt][nt][2] + bHi, acc[mt][nt][3] + bHi);
            *reinterpret_cast<float2*>(dst + (size_t)d0 * NL + l)       = r0;
            *reinterpret_cast<float2*>(dst + (size_t)(d0 + 8) * NL + l) = r1;
        }
    }
}

// ---------------------------------------------------------------------------
// Kernel 2: corr via FFT (reference algorithm):
//   corr = real(ifft(fft(q) * conj(fft(k))))
// Two series (d0, d0+1) per CTA. NOW 256 THREADS: same indexing, half the
// serial iterations per sync region. Top-13 (ties -> lowest index), softmax,
// weighted circular v-gather.
// ---------------------------------------------------------------------------
__global__ __launch_bounds__(256) void corr_kernel()
{
    __shared__ __align__(16) float2 fbuf[4096];   // 32 KB workspace
    __shared__ float2 tw[512];
    __shared__ float s_tv[2][KTOP];
    __shared__ int   s_ti[2][KTOP];
    __shared__ float s_w[2][KTOP];
    __shared__ float red_v[8];
    __shared__ int   red_i[8];

    const int b   = blockIdx.y;
    const int d0  = blockIdx.x * 2;
    const int tid = threadIdx.x;
    float* fbf = reinterpret_cast<float*>(fbuf);
    const size_t offA = ((size_t)b * NDH + d0) * NL;

    for (int j = tid; j < 512; j += 256) {
        float s, c;
        sincospif(-(float)j / 512.0f, &s, &c);
        tw[j] = make_float2(c, s);
    }
    {
        const float4* qa = reinterpret_cast<const float4*>(g_qp + offA);
        const float4* ka = reinterpret_cast<const float4*>(g_kp + offA);
        for (int i = tid; i < 512; i += 256) {
            float4 q = qa[i], k = ka[i];
            int o = i * 4;
            fbuf[o+0] = make_float2(q.x, k.x);
            fbuf[o+1] = make_float2(q.y, k.y);
            fbuf[o+2] = make_float2(q.z, k.z);
            fbuf[o+3] = make_float2(q.w, k.w);
        }
    }
    __syncthreads();

    // forward FFT, both series at once, ping-pong 0<->2048
    int src = 0;
    for (int st = 0; st < 10; ++st) {
        const int s = 1 << st;
        const int dst = src ^ 2048;
        #pragma unroll 2
        for (int it = 0; it < 4; ++it) {
            int t  = tid + it * 256;
            int so = (t >> 9) << 10;
            int u  = t & 511;
            int j  = u & ~(s - 1);
            float2 a  = fbuf[src + so + u];
            float2 bb = fbuf[src + so + u + 512];
            float2 w  = tw[j];
            float2 df = make_float2(a.x - bb.x, a.y - bb.y);
            fbuf[dst + so + u + j]     = make_float2(a.x + bb.x, a.y + bb.y);
            fbuf[dst + so + u + j + s] = make_float2(w.x*df.x - w.y*df.y,
                                                     w.x*df.y + w.y*df.x);
        }
        __syncthreads();
        src = dst;
    }

    // spectral: S = Q * conj(K); T = S_a + i*S_b; store conj(T) in [2048,3072)
    for (int it = 0; it < 4; ++it) {
        int f  = tid + it * 256;
        int fn = (1024 - f) & 1023;
        float2 Za = fbuf[f],        Zan = fbuf[fn];
        float2 Zb = fbuf[1024 + f], Zbn = fbuf[1024 + fn];
        float qx = 0.5f*(Za.x + Zan.x), qy = 0.5f*(Za.y - Zan.y);
        float kx = 0.5f*(Za.y + Zan.y), ky = -0.5f*(Za.x - Zan.x);
        float sax = qx*kx + qy*ky, say = qy*kx - qx*ky;
        float qx2 = 0.5f*(Zb.x + Zbn.x), qy2 = 0.5f*(Zb.y - Zbn.y);
        float kx2 = 0.5f*(Zb.y + Zbn.y), ky2 = -0.5f*(Zb.x - Zbn.x);
        float sbx = qx2*kx2 + qy2*ky2, sby = qy2*kx2 - qx2*ky2;
        fbuf[2048 + f] = make_float2(sax - sby, -(say + sbx));
    }
    __syncthreads();

    // load v for both series into floats [6144,8192)
    {
        const float4* va = reinterpret_cast<const float4*>(g_vp + offA);
        for (int i = tid; i < 512; i += 256)
            *reinterpret_cast<float4*>(&fbf[6144 + i * 4]) = va[i];
    }

    // inverse FFT (forward FFT of conj T), ping-pong [2048,3072) <-> [0,1024)
    int s2 = 2048;
    for (int st = 0; st < 10; ++st) {
        const int s = 1 << st;
        const int dst = (s2 == 2048) ? 0 : 2048;
        #pragma unroll 2
        for (int it = 0; it < 2; ++it) {
            int u = tid + it * 256;
            int j = u & ~(s - 1);
            float2 a  = fbuf[s2 + u];
            float2 bb = fbuf[s2 + u + 512];
            float2 w  = tw[j];
            float2 df = make_float2(a.x - bb.x, a.y - bb.y);
            fbuf[dst + u + j]     = make_float2(a.x + bb.x, a.y + bb.y);
            fbuf[dst + u + j + s] = make_float2(w.x*df.x - w.y*df.y,
                                                w.x*df.y + w.y*df.x);
        }
        __syncthreads();
        s2 = dst;
    }

    const float invN = 1.0f / 1024.0f;
    for (int it = 0; it < 4; ++it) {
        int n = tid + it * 256;
        float2 F = fbuf[2048 + n];
        fbf[n]        =  F.x * invN;
        fbf[1024 + n] = -F.y * invN;
    }
    __syncthreads();

    // top-13 per series: threads 0-127 -> series A, 128-255 -> series B
    const int sid = tid >> 7;
    const int lt  = tid & 127;
    float* sc = fbf + (sid << 10);
    const int base = lt * 8;
    for (int p = 0; p < KTOP; ++p) {
        float bv = -3.0e38f; int bi = 0;
        #pragma unroll
        for (int jj = 0; jj < 8; ++jj) {
            float v = sc[base + jj];
            if (v > bv) { bv = v; bi = base + jj; }   // asc idx -> low-idx tie
        }
        #pragma unroll
        for (int off = 16; off > 0; off >>= 1) {
            float ov = __shfl_down_sync(0xffffffffu, bv, off);
            int   oi = __shfl_down_sync(0xffffffffu, bi, off);
            if (ov > bv || (ov == bv && oi < bi)) { bv = ov; bi = oi; }
        }
        if ((tid & 31) == 0) { red_v[tid >> 5] = bv; red_i[tid >> 5] = bi; }
        __syncthreads();
        if (lt == 0) {
            float v0 = red_v[sid * 4]; int i0 = red_i[sid * 4];
            #pragma unroll
            for (int w = 1; w < 4; ++w) {
                float v1 = red_v[sid * 4 + w]; int i1 = red_i[sid * 4 + w];
                if (v1 > v0 || (v1 == v0 && i1 < i0)) { v0 = v1; i0 = i1; }
            }
            s_tv[sid][p] = v0; s_ti[sid][p] = i0;
            sc[i0] = -3.4e38f;
        }
        __syncthreads();
    }

    if (lt == 0) {
        float mx = s_tv[sid][0];
        float e[KTOP], sum = 0.f;
        #pragma unroll
        for (int p = 0; p < KTOP; ++p) { e[p] = expf(s_tv[sid][p] - mx); sum += e[p]; }
        float inv = 1.0f / sum;
        #pragma unroll
        for (int p = 0; p < KTOP; ++p) s_w[sid][p] = e[p] * inv;
    }
    __syncthreads();

    const float* sv = fbf + 6144 + (sid << 10);
    float* aggrow = g_agg + offA + (size_t)sid * NL;
    float wgt[KTOP]; int ix[KTOP];
    #pragma unroll
    for (int p = 0; p < KTOP; ++p) { wgt[p] = s_w[sid][p]; ix[p] = s_ti[sid][p]; }
    #pragma unroll
    for (int jj = 0; jj < 8; ++jj) {
        int l = lt + jj * 128;
        float acc = 0.f;
        #pragma unroll
        for (int p = 0; p < KTOP; ++p)
            acc += wgt[p] * sv[(l + ix[p]) & 1023];
        aggrow[l] = acc;
    }
}

// ---------------------------------------------------------------------------
// Kernel 3: transpose-broadcast agg[b][d][l] -> out[b][l][h*64+d], h=0..7
// ---------------------------------------------------------------------------
__global__ __launch_bounds__(256) void out_kernel(float* __restrict__ out)
{
    __shared__ float t[64][33];
    const int b   = blockIdx.y;
    const int l0  = blockIdx.x * 32;
    const int tid = threadIdx.x;
    const float* agg = g_agg + (size_t)b * NDH * NL;

    #pragma unroll
    for (int i = 0; i < 8; ++i) {
        int flat = tid + i * 256;
        int dd   = flat >> 5;
        int ll   = flat & 31;
        t[dd][ll] = agg[(size_t)dd * NL + l0 + ll];
    }
    __syncthreads();

    float* obase = out + ((size_t)b * NL + l0) * (NDH * 8);
    #pragma unroll
    for (int i = 0; i < 16; ++i) {
        int f4  = tid + i * 256;
        int ll  = f4 >> 7;
        int c0  = (f4 & 127) * 4;
        int cc  = c0 & 63;
        float4 v = make_float4(t[cc][ll], t[cc + 1][ll], t[cc + 2][ll], t[cc + 3][ll]);
        *reinterpret_cast<float4*>(obase + (size_t)ll * 512 + c0) = v;
    }
}

// ---------------------------------------------------------------------------
extern "C" void kernel_launch(void* const* d_in, const int* in_sizes, int n_in,
                              void* d_out, int out_size)
{
    const float* Q  = (const float*)d_in[0];
    const float* K  = (const float*)d_in[1];
    const float* V  = (const float*)d_in[2];
    const float* Wq = (const float*)d_in[3];
    const float* bq = (const float*)d_in[4];
    float* out = (float*)d_out;

    proj_kernel<<<dim3(NL / 128, NB, 3), 256>>>(Q, K, V, Wq, bq);
    corr_kernel<<<dim3(NDH / 2, NB), 256>>>();
    out_kernel<<<dim3(NL / 32, NB), 256>>>(out);
}

// round 14
// speedup vs baseline: 1.0778x; 1.0356x over previous
#include <cuda_runtime.h>
#include <math.h>

#define NB   16
#define NL   1024
#define ND   512
#define NDH  64
#define KTOP 13

// Scratch (no allocations allowed): 4 x 4MB fp32
__device__ float g_qp[NB * NDH * NL];   // q projection, [b][d][l]
__device__ float g_kp[NB * NDH * NL];   // k projection, [b][d][l]
__device__ float g_vp[NB * NDH * NL];   // v projection, [b][d][l]
__device__ float g_agg[NB * NDH * NL];  // aggregated result, [b][d][l]

// ---- bf16 split helpers (truncation split) --------------------------------
__device__ __forceinline__ void split_dup(float x, unsigned& wh, unsigned& wl) {
    unsigned u = __float_as_uint(x);
    float hi = __uint_as_float(u & 0xFFFF0000u);
    unsigned lu = __float_as_uint(x - hi);
    wh = __byte_perm(u,  u,  0x3232);
    wl = __byte_perm(lu, lu, 0x3232);
}
__device__ __forceinline__ unsigned split_pack(float x) {
    unsigned u = __float_as_uint(x);
    float hi = __uint_as_float(u & 0xFFFF0000u);
    unsigned lu = __float_as_uint(x - hi);
    return __byte_perm(u, lu, 0x7632);
}

__device__ __forceinline__ void mma_bf16(float* c, const unsigned* a,
                                         unsigned b0, unsigned b1) {
    asm volatile(
        "mma.sync.aligned.m16n8k16.row.col.f32.bf16.bf16.f32 "
        "{%0,%1,%2,%3}, {%4,%5,%6,%7}, {%8,%9}, {%0,%1,%2,%3};\n"
        : "+f"(c[0]), "+f"(c[1]), "+f"(c[2]), "+f"(c[3])
        : "r"(a[0]), "r"(a[1]), "r"(a[2]), "r"(a[3]), "r"(b0), "r"(b1));
}

__device__ __forceinline__ int smidx(int row, int w) {
    return row * 32 + (((w >> 3) ^ (row & 3)) << 3)
         + ((w & 7) ^ (((row >> 2) & 1) << 2));
}

// ---------------------------------------------------------------------------
// Kernel 1: projection via bf16 tensor cores, split-K doubling.
// R7 exact (best measured: 56.8us). BK=32, single-buffered static smem,
// register prefetch. grid (NL/128, NB, 3), 256 threads.
// ---------------------------------------------------------------------------
__global__ __launch_bounds__(256) void proj_kernel(
    const float* __restrict__ Q, const float* __restrict__ K,
    const float* __restrict__ V, const float* __restrict__ Wq,
    const float* __restrict__ bq)
{
    __shared__ unsigned Ws[64 * 32];
    __shared__ unsigned Xh[128 * 32];
    __shared__ unsigned Xl[128 * 32];

    const int b    = blockIdx.y;
    const int l0   = blockIdx.x * 128;
    const int mat  = blockIdx.z;
    const int tid  = threadIdx.x;
    const int wid  = tid >> 5;
    const int lane = tid & 31;
    const int g    = lane >> 2;
    const int cq   = lane & 3;
    const int m_base = (wid >> 2) * 32;
    const int n_base = (wid & 3) * 32;

    const float* src = (mat == 0 ? Q : (mat == 1 ? K : V))
                     + ((size_t)b * NL + l0) * ND;
    float* dst = (mat == 0 ? g_qp : (mat == 1 ? g_kp : g_vp))
               + (size_t)b * NDH * NL + l0;

    int xgb[4], xsb[4];
    #pragma unroll
    for (int i = 0; i < 4; ++i) {
        int f4id = tid + i * 256;
        int r    = f4id >> 3;
        int c4   = f4id & 7;
        xgb[i]   = r * ND + c4 * 4;
        xsb[i]   = r * 32 + (((c4 >> 1) ^ (r & 3)) << 3)
                 + (((c4 & 1) << 2) ^ (((r >> 2) & 1) << 2));
    }
    int wdd[2], wkq[2], wsb[2];
    #pragma unroll
    for (int i = 0; i < 2; ++i) {
        int qid = tid + i * 256;
        wdd[i]  = qid & 63;
        wkq[i]  = qid >> 6;
        wsb[i]  = wdd[i] * 32 + (((wkq[i] >> 1) ^ (wdd[i] & 3)) << 3)
                + (((wkq[i] & 1) << 2) ^ (((wdd[i] >> 2) & 1) << 2));
    }

    float acc[2][4][4];
    #pragma unroll
    for (int mt = 0; mt < 2; ++mt)
        #pragma unroll
        for (int nt = 0; nt < 4; ++nt)
            #pragma unroll
            for (int r = 0; r < 4; ++r) acc[mt][nt][r] = 0.f;

    float4 xR[4];
    float  wF[8];
    #pragma unroll
    for (int i = 0; i < 4; ++i)
        xR[i] = *reinterpret_cast<const float4*>(src + xgb[i]);
    #pragma unroll
    for (int i = 0; i < 2; ++i)
        #pragma unroll
        for (int j = 0; j < 4; ++j)
            wF[i * 4 + j] = Wq[(size_t)(wkq[i] * 4 + j) * NDH + wdd[i]];

    for (int ch = 0; ch < 16; ++ch) {
        #pragma unroll
        for (int i = 0; i < 4; ++i) {
            unsigned h0,h1,h2,h3, q0,q1,q2,q3;
            split_dup(xR[i].x, h0, q0);
            split_dup(xR[i].y, h1, q1);
            split_dup(xR[i].z, h2, q2);
            split_dup(xR[i].w, h3, q3);
            *reinterpret_cast<uint4*>(&Xh[xsb[i]]) = make_uint4(h0,h1,h2,h3);
            *reinterpret_cast<uint4*>(&Xl[xsb[i]]) = make_uint4(q0,q1,q2,q3);
        }
        #pragma unroll
        for (int i = 0; i < 2; ++i) {
            *reinterpret_cast<uint4*>(&Ws[wsb[i]]) = make_uint4(
                split_pack(wF[i*4+0]), split_pack(wF[i*4+1]),
                split_pack(wF[i*4+2]), split_pack(wF[i*4+3]));
        }
        __syncthreads();

        if (ch < 15) {
            const int ko = (ch + 1) * 32;
            #pragma unroll
            for (int i = 0; i < 4; ++i)
                xR[i] = *reinterpret_cast<const float4*>(src + xgb[i] + ko);
            #pragma unroll
            for (int i = 0; i < 2; ++i)
                #pragma unroll
                for (int j = 0; j < 4; ++j)
                    wF[i * 4 + j] = Wq[(size_t)(ko + wkq[i] * 4 + j) * NDH + wdd[i]];
        }

        #pragma unroll
        for (int ks = 0; ks < 4; ++ks) {
            unsigned a[2][4];
            #pragma unroll
            for (int mt = 0; mt < 2; ++mt) {
                int r0 = m_base + mt * 16 + g;
                a[mt][0] = Ws[smidx(r0,     ks * 8 + cq)];
                a[mt][1] = Ws[smidx(r0 + 8, ks * 8 + cq)];
                a[mt][2] = Ws[smidx(r0,     ks * 8 + cq + 4)];
                a[mt][3] = Ws[smidx(r0 + 8, ks * 8 + cq + 4)];
            }
            #pragma unroll
            for (int nt = 0; nt < 4; ++nt) {
                int rn = n_base + nt * 8 + g;
                unsigned bh0 = Xh[smidx(rn, ks * 8 + cq)];
                unsigned bh1 = Xh[smidx(rn, ks * 8 + cq + 4)];
                unsigned bl0 = Xl[smidx(rn, ks * 8 + cq)];
                unsigned bl1 = Xl[smidx(rn, ks * 8 + cq + 4)];
                #pragma unroll
                for (int mt = 0; mt < 2; ++mt) {
                    mma_bf16(acc[mt][nt], a[mt], bh0, bh1);
                    mma_bf16(acc[mt][nt], a[mt], bl0, bl1);
                }
            }
        }
        __syncthreads();
    }

    #pragma unroll
    for (int mt = 0; mt < 2; ++mt) {
        int d0 = m_base + mt * 16 + g;
        float bLo = bq[d0];
        float bHi = bq[d0 + 8];
        #pragma unroll
        for (int nt = 0; nt < 4; ++nt) {
            int l = n_base + nt * 8 + 2 * cq;
            float2 r0 = make_float2(acc[mt][nt][0] + bLo, acc[mt][nt][1] + bLo);
            float2 r1 = make_float2(acc[mt][nt][2] + bHi, acc[mt][nt][3] + bHi);
            *reinterpret_cast<float2*>(dst + (size_t)d0 * NL + l)       = r0;
            *reinterpret_cast<float2*>(dst + (size_t)(d0 + 8) * NL + l) = r1;
        }
    }
}

// ---------------------------------------------------------------------------
// Kernel 2: corr via FFT (reference algorithm):
//   corr = real(ifft(fft(q) * conj(fft(k))))
// Two series (d0, d0+1) per CTA, 256 threads. FUSED radix-2^2 double stages:
// each thread does two consecutive radix-2 Stockham stages in registers
// (identical arithmetic, half the barriers/smem round-trips: 10 -> 5 per FFT).
// Then top-13 (ties -> lowest index), softmax, weighted circular v-gather.
// ---------------------------------------------------------------------------
__global__ __launch_bounds__(256) void corr_kernel()
{
    __shared__ __align__(16) float2 fbuf[4096];   // 32 KB workspace
    __shared__ float2 tw[512];
    __shared__ float s_tv[2][KTOP];
    __shared__ int   s_ti[2][KTOP];
    __shared__ float s_w[2][KTOP];
    __shared__ float red_v[8];
    __shared__ int   red_i[8];

    const int b   = blockIdx.y;
    const int d0  = blockIdx.x * 2;
    const int tid = threadIdx.x;
    float* fbf = reinterpret_cast<float*>(fbuf);
    const size_t offA = ((size_t)b * NDH + d0) * NL;

    for (int j = tid; j < 512; j += 256) {
        float s, c;
        sincospif(-(float)j / 512.0f, &s, &c);
        tw[j] = make_float2(c, s);
    }
    {
        const float4* qa = reinterpret_cast<const float4*>(g_qp + offA);
        const float4* ka = reinterpret_cast<const float4*>(g_kp + offA);
        for (int i = tid; i < 512; i += 256) {
            float4 q = qa[i], k = ka[i];
            int o = i * 4;
            fbuf[o+0] = make_float2(q.x, k.x);
            fbuf[o+1] = make_float2(q.y, k.y);
            fbuf[o+2] = make_float2(q.z, k.z);
            fbuf[o+3] = make_float2(q.w, k.w);
        }
    }
    __syncthreads();

    // forward FFT, both series, 5 fused double-stages, ping-pong 0<->2048.
    // After 5 swaps the result lands in [2048, 4096).
    int src = 0;
    for (int fs = 0; fs < 5; ++fs) {
        const int s  = 1 << (2 * fs);
        const int s2 = s << 1;
        const int dst = src ^ 2048;
        #pragma unroll 2
        for (int it = 0; it < 2; ++it) {
            int t  = tid + it * 256;
            int so = (t >> 8) << 10;        // series offset
            int u  = t & 255;
            int j  = u & ~(s - 1);
            float2 x0 = fbuf[src + so + u];
            float2 x1 = fbuf[src + so + u + 256];
            float2 x2 = fbuf[src + so + u + 512];
            float2 x3 = fbuf[src + so + u + 768];
            // sub-stage st on (x0,x2)@u and (x1,x3)@u+256
            float2 w0 = tw[j];
            float2 w1 = tw[j + 256];
            float2 y0 = make_float2(x0.x + x2.x, x0.y + x2.y);
            float2 dA = make_float2(x0.x - x2.x, x0.y - x2.y);
            float2 y1 = make_float2(w0.x*dA.x - w0.y*dA.y, w0.x*dA.y + w0.y*dA.x);
            float2 y2 = make_float2(x1.x + x3.x, x1.y + x3.y);
            float2 dB = make_float2(x1.x - x3.x, x1.y - x3.y);
            float2 y3 = make_float2(w1.x*dB.x - w1.y*dB.y, w1.x*dB.y + w1.y*dB.x);
            // sub-stage st+1 on (y0,y2)@a and (y1,y3)@a+s
            int a  = u + j;
            int ja = a & ~(s2 - 1);
            int jb = (a + s) & ~(s2 - 1);
            float2 wa = tw[ja];
            float2 wb = tw[jb];
            float2 dC = make_float2(y0.x - y2.x, y0.y - y2.y);
            fbuf[dst + so + a + ja]      = make_float2(y0.x + y2.x, y0.y + y2.y);
            fbuf[dst + so + a + ja + s2] =
                make_float2(wa.x*dC.x - wa.y*dC.y, wa.x*dC.y + wa.y*dC.x);
            float2 dD = make_float2(y1.x - y3.x, y1.y - y3.y);
            fbuf[dst + so + a + s + jb]      = make_float2(y1.x + y3.x, y1.y + y3.y);
            fbuf[dst + so + a + s + jb + s2] =
                make_float2(wb.x*dD.x - wb.y*dD.y, wb.x*dD.y + wb.y*dD.x);
        }
        __syncthreads();
        src = dst;
    }
    // forward result in [2048, 4096)

    // spectral: S = Q * conj(K); T = S_a + i*S_b; write conj(T) to [0,1024)
    // (reads [2048,4096) only — no overlap with writes, no race)
    for (int it = 0; it < 4; ++it) {
        int f  = tid + it * 256;
        int fn = (1024 - f) & 1023;
        float2 Za = fbuf[2048 + f],  Zan = fbuf[2048 + fn];
        float2 Zb = fbuf[3072 + f],  Zbn = fbuf[3072 + fn];
        float qx = 0.5f*(Za.x + Zan.x), qy = 0.5f*(Za.y - Zan.y);
        float kx = 0.5f*(Za.y + Zan.y), ky = -0.5f*(Za.x - Zan.x);
        float sax = qx*kx + qy*ky, say = qy*kx - qx*ky;
        float qx2 = 0.5f*(Zb.x + Zbn.x), qy2 = 0.5f*(Zb.y - Zbn.y);
        float kx2 = 0.5f*(Zb.y + Zbn.y), ky2 = -0.5f*(Zb.x - Zbn.x);
        float sbx = qx2*kx2 + qy2*ky2, sby = qy2*kx2 - qx2*ky2;
        fbuf[f] = make_float2(sax - sby, -(say + sbx));
    }
    __syncthreads();

    // load v for both series into floats [6144,8192) (forward result dead)
    {
        const float4* va = reinterpret_cast<const float4*>(g_vp + offA);
        for (int i = tid; i < 512; i += 256)
            *reinterpret_cast<float4*>(&fbf[6144 + i * 4]) = va[i];
    }

    // inverse FFT (forward FFT of conj T), 5 fused double-stages,
    // ping-pong [0,1024) <-> [2048,3072). Ends in [2048,3072).
    int s2v = 0;
    for (int fs = 0; fs < 5; ++fs) {
        const int s  = 1 << (2 * fs);
        const int s2 = s << 1;
        const int dst = (s2v == 0) ? 2048 : 0;
        {
            int u  = tid;
            int j  = u & ~(s - 1);
            float2 x0 = fbuf[s2v + u];
            float2 x1 = fbuf[s2v + u + 256];
            float2 x2 = fbuf[s2v + u + 512];
            float2 x3 = fbuf[s2v + u + 768];
            float2 w0 = tw[j];
            float2 w1 = tw[j + 256];
            float2 y0 = make_float2(x0.x + x2.x, x0.y + x2.y);
            float2 dA = make_float2(x0.x - x2.x, x0.y - x2.y);
            float2 y1 = make_float2(w0.x*dA.x - w0.y*dA.y, w0.x*dA.y + w0.y*dA.x);
            float2 y2 = make_float2(x1.x + x3.x, x1.y + x3.y);
            float2 dB = make_float2(x1.x - x3.x, x1.y - x3.y);
            float2 y3 = make_float2(w1.x*dB.x - w1.y*dB.y, w1.x*dB.y + w1.y*dB.x);
            int a  = u + j;
            int ja = a & ~(s2 - 1);
            int jb = (a + s) & ~(s2 - 1);
            float2 wa = tw[ja];
            float2 wb = tw[jb];
            float2 dC = make_float2(y0.x - y2.x, y0.y - y2.y);
            fbuf[dst + a + ja]      = make_float2(y0.x + y2.x, y0.y + y2.y);
            fbuf[dst + a + ja + s2] =
                make_float2(wa.x*dC.x - wa.y*dC.y, wa.x*dC.y + wa.y*dC.x);
            float2 dD = make_float2(y1.x - y3.x, y1.y - y3.y);
            fbuf[dst + a + s + jb]      = make_float2(y1.x + y3.x, y1.y + y3.y);
            fbuf[dst + a + s + jb + s2] =
                make_float2(wb.x*dD.x - wb.y*dD.y, wb.x*dD.y + wb.y*dD.x);
        }
        __syncthreads();
        s2v = dst;
    }
    // result in [2048,3072): ifft = conj(F)/N -> corr_a = Re/N, corr_b = -Im/N

    const float invN = 1.0f / 1024.0f;
    for (int it = 0; it < 4; ++it) {
        int n = tid + it * 256;
        float2 F = fbuf[2048 + n];
        fbf[n]        =  F.x * invN;
        fbf[1024 + n] = -F.y * invN;
    }
    __syncthreads();

    // top-13 per series: threads 0-127 -> series A, 128-255 -> series B
    const int sid = tid >> 7;
    const int lt  = tid & 127;
    float* sc = fbf + (sid << 10);
    const int base = lt * 8;
    for (int p = 0; p < KTOP; ++p) {
        float bv = -3.0e38f; int bi = 0;
        #pragma unroll
        for (int jj = 0; jj < 8; ++jj) {
            float v = sc[base + jj];
            if (v > bv) { bv = v; bi = base + jj; }   // asc idx -> low-idx tie
        }
        #pragma unroll
        for (int off = 16; off > 0; off >>= 1) {
            float ov = __shfl_down_sync(0xffffffffu, bv, off);
            int   oi = __shfl_down_sync(0xffffffffu, bi, off);
            if (ov > bv || (ov == bv && oi < bi)) { bv = ov; bi = oi; }
        }
        if ((tid & 31) == 0) { red_v[tid >> 5] = bv; red_i[tid >> 5] = bi; }
        __syncthreads();
        if (lt == 0) {
            float v0 = red_v[sid * 4]; int i0 = red_i[sid * 4];
            #pragma unroll
            for (int w = 1; w < 4; ++w) {
                float v1 = red_v[sid * 4 + w]; int i1 = red_i[sid * 4 + w];
                if (v1 > v0 || (v1 == v0 && i1 < i0)) { v0 = v1; i0 = i1; }
            }
            s_tv[sid][p] = v0; s_ti[sid][p] = i0;
            sc[i0] = -3.4e38f;
        }
        __syncthreads();
    }

    if (lt == 0) {
        float mx = s_tv[sid][0];
        float e[KTOP], sum = 0.f;
        #pragma unroll
        for (int p = 0; p < KTOP; ++p) { e[p] = expf(s_tv[sid][p] - mx); sum += e[p]; }
        float inv = 1.0f / sum;
        #pragma unroll
        for (int p = 0; p < KTOP; ++p) s_w[sid][p] = e[p] * inv;
    }
    __syncthreads();

    const float* sv = fbf + 6144 + (sid << 10);
    float* aggrow = g_agg + offA + (size_t)sid * NL;
    float wgt[KTOP]; int ix[KTOP];
    #pragma unroll
    for (int p = 0; p < KTOP; ++p) { wgt[p] = s_w[sid][p]; ix[p] = s_ti[sid][p]; }
    #pragma unroll
    for (int jj = 0; jj < 8; ++jj) {
        int l = lt + jj * 128;
        float acc = 0.f;
        #pragma unroll
        for (int p = 0; p < KTOP; ++p)
            acc += wgt[p] * sv[(l + ix[p]) & 1023];
        aggrow[l] = acc;
    }
}

// ---------------------------------------------------------------------------
// Kernel 3: transpose-broadcast agg[b][d][l] -> out[b][l][h*64+d], h=0..7
// ---------------------------------------------------------------------------
__global__ __launch_bounds__(256) void out_kernel(float* __restrict__ out)
{
    __shared__ float t[64][33];
    const int b   = blockIdx.y;
    const int l0  = blockIdx.x * 32;
    const int tid = threadIdx.x;
    const float* agg = g_agg + (size_t)b * NDH * NL;

    #pragma unroll
    for (int i = 0; i < 8; ++i) {
        int flat = tid + i * 256;
        int dd   = flat >> 5;
        int ll   = flat & 31;
        t[dd][ll] = agg[(size_t)dd * NL + l0 + ll];
    }
    __syncthreads();

    float* obase = out + ((size_t)b * NL + l0) * (NDH * 8);
    #pragma unroll
    for (int i = 0; i < 16; ++i) {
        int f4  = tid + i * 256;
        int ll  = f4 >> 7;
        int c0  = (f4 & 127) * 4;
        int cc  = c0 & 63;
        float4 v = make_float4(t[cc][ll], t[cc + 1][ll], t[cc + 2][ll], t[cc + 3][ll]);
        *reinterpret_cast<float4*>(obase + (size_t)ll * 512 + c0) = v;
    }
}

// ---------------------------------------------------------------------------
extern "C" void kernel_launch(void* const* d_in, const int* in_sizes, int n_in,
                              void* d_out, int out_size)
{
    const float* Q  = (const float*)d_in[0];
    const float* K  = (const float*)d_in[1];
    const float* V  = (const float*)d_in[2];
    const float* Wq = (const float*)d_in[3];
    const float* bq = (const float*)d_in[4];
    float* out = (float*)d_out;

    proj_kernel<<<dim3(NL / 128, NB, 3), 256>>>(Q, K, V, Wq, bq);
    corr_kernel<<<dim3(NDH / 2, NB), 256>>>();
    out_kernel<<<dim3(NL / 32, NB), 256>>>(out);
}